// round 3
// baseline (speedup 1.0000x reference)
#include <cuda_runtime.h>
#include <cuda_fp16.h>
#include <cstdint>
#include <cstddef>

// ---------------- problem constants ----------------
#define NE    8
#define D_IN  2048
#define H_FF  5632
#define T_TOK 8192
#define PAIRS 16384
#define XROWS (PAIRS + 128)      // padded so GEMM tiles never read OOB

// ---------------- GEMM tiling ----------------
#define BM 128
#define BN 128
#define BK 64
#define MAX_TILES 136            // sum_e ceil(c_e/128) <= 128 + 8
#define GEMM_THREADS 256
#define NSTAGES 3
#define A_BYTES (BM * BK * 2)    // 16384
#define B_BYTES (BN * BK * 2)    // 16384
#define STAGE_BYTES (A_BYTES + B_BYTES)       // 32768
#define SMEM_TOTAL (NSTAGES * STAGE_BYTES)    // 98304

// ---------------- device scratch (static globals; no allocation) ----------------
__device__ __half g_wup[(size_t)NE * 2 * H_FF * D_IN];   // fp16 gate+up weights
__device__ __half g_wdn[(size_t)NE * D_IN * H_FF];       // fp16 down weights
__device__ __half g_xh [(size_t)XROWS * D_IN];           // gathered fp16 inputs (sorted by expert)
__device__ __half g_act[(size_t)XROWS * H_FF];           // SwiGLU activations
__device__ int   g_cnt[NE];
__device__ int   g_cur[NE];
__device__ int   g_off[NE];
__device__ int   g_rtok[PAIRS];
__device__ float g_rw  [PAIRS];
__device__ int   g_te [MAX_TILES];
__device__ int   g_tm0[MAX_TILES];
__device__ int   g_tm1[MAX_TILES];
__device__ int   g_ntiles;

// ---------------- PTX helpers ----------------
__device__ __forceinline__ uint32_t smem_u32(const void* p) {
    uint32_t a;
    asm("{ .reg .u64 t; cvta.to.shared.u64 t, %1; cvt.u32.u64 %0, t; }" : "=r"(a) : "l"(p));
    return a;
}
__device__ __forceinline__ void cp_async16(uint32_t dst, const void* src) {
    asm volatile("cp.async.cg.shared.global [%0], [%1], 16;" :: "r"(dst), "l"(src));
}
__device__ __forceinline__ void cp_commit() { asm volatile("cp.async.commit_group;" ::: "memory"); }
__device__ __forceinline__ void cp_wait1()  { asm volatile("cp.async.wait_group 1;" ::: "memory"); }

__device__ __forceinline__ void ldsm4(uint32_t* r, uint32_t addr) {
    asm volatile("ldmatrix.sync.aligned.m8n8.x4.shared.b16 {%0,%1,%2,%3}, [%4];"
                 : "=r"(r[0]), "=r"(r[1]), "=r"(r[2]), "=r"(r[3]) : "r"(addr));
}
__device__ __forceinline__ void mma16816(float* c, const uint32_t* a, uint32_t b0, uint32_t b1) {
    asm volatile(
        "mma.sync.aligned.m16n8k16.row.col.f32.f16.f16.f32 "
        "{%0,%1,%2,%3}, {%4,%5,%6,%7}, {%8,%9}, {%0,%1,%2,%3};"
        : "+f"(c[0]), "+f"(c[1]), "+f"(c[2]), "+f"(c[3])
        : "r"(a[0]), "r"(a[1]), "r"(a[2]), "r"(a[3]), "r"(b0), "r"(b1));
}

// ---------------- small kernels ----------------
__global__ void k_route_init() {
    int i = threadIdx.x;
    if (i < NE) { g_cnt[i] = 0; g_cur[i] = 0; }
}
__global__ void k_count(const int* __restrict__ ids) {
    int p = blockIdx.x * blockDim.x + threadIdx.x;
    if (p < PAIRS) atomicAdd(&g_cnt[ids[p]], 1);
}
__global__ void k_offsets() {
    if (threadIdx.x == 0) {
        int off = 0, slot = 0;
        for (int e = 0; e < NE; e++) {
            g_off[e] = off;
            int c = g_cnt[e];
            for (int m = 0; m < c; m += BM) {
                g_te[slot]  = e;
                g_tm0[slot] = off + m;
                g_tm1[slot] = off + ((m + BM < c) ? (m + BM) : c);
                slot++;
            }
            off += c;
        }
        g_ntiles = slot;
    }
}
__global__ void k_scatter(const float* __restrict__ x, const float* __restrict__ tw,
                          const int* __restrict__ ids) {
    int p = blockIdx.x;            // pair index
    int t = p >> 1;
    __shared__ int spos;
    if (threadIdx.x == 0) {
        int e   = ids[p];
        int pos = g_off[e] + atomicAdd(&g_cur[e], 1);
        g_rtok[pos] = t;
        g_rw[pos]   = tw[p];
        spos = pos;
    }
    __syncthreads();
    int pos = spos;
    const float4* src = (const float4*)(x + (size_t)t * D_IN);
    uint2* dst = (uint2*)(g_xh + (size_t)pos * D_IN);
    for (int i = threadIdx.x; i < D_IN / 4; i += 256) {
        float4 v = src[i];
        __half2 a = __floats2half2_rn(v.x, v.y);
        __half2 b = __floats2half2_rn(v.z, v.w);
        uint2 o;
        o.x = *reinterpret_cast<uint32_t*>(&a);
        o.y = *reinterpret_cast<uint32_t*>(&b);
        dst[i] = o;
    }
}
__global__ void k_convert(const float* __restrict__ s, int which) {
    __half* d = which ? g_wdn : g_wup;
    size_t n4 = (which ? ((size_t)NE * D_IN * H_FF) : ((size_t)NE * 2 * H_FF * D_IN)) >> 2;
    size_t stride = (size_t)gridDim.x * blockDim.x;
    for (size_t i = (size_t)blockIdx.x * blockDim.x + threadIdx.x; i < n4; i += stride) {
        float4 v = ((const float4*)s)[i];
        __half2 a = __floats2half2_rn(v.x, v.y);
        __half2 b = __floats2half2_rn(v.z, v.w);
        uint2 o;
        o.x = *reinterpret_cast<uint32_t*>(&a);
        o.y = *reinterpret_cast<uint32_t*>(&b);
        ((uint2*)d)[i] = o;
    }
}
__global__ void k_zero(float* __restrict__ out) {
    size_t n4 = ((size_t)T_TOK * D_IN) >> 2;
    float4 z = make_float4(0.f, 0.f, 0.f, 0.f);
    size_t stride = (size_t)gridDim.x * blockDim.x;
    for (size_t i = (size_t)blockIdx.x * blockDim.x + threadIdx.x; i < n4; i += stride)
        ((float4*)out)[i] = z;
}

// ---------------- grouped GEMM (mma.sync m16n8k16, 3-stage cp.async, SW128 smem) ----------------
// G1: A = g_xh [rows, 2048]; B smem row r (r=0..127): h = n0h + (r>>1), weight row
//     (r even ? h : H_FF + h) of g_wup[e]  -> lane accum pair (c0,c1) = (gate,up) of same h
//     -> SwiGLU -> g_act.
// G2: A = g_act [rows, 5632]; B = g_wdn[e] rows n0..n0+127 -> w * y atomicAdd into out.
template<bool G1>
__global__ void __launch_bounds__(GEMM_THREADS, 1) k_gemm(float* __restrict__ out) {
    extern __shared__ char smem[];
    const int slot = blockIdx.x;
    if (slot >= g_ntiles) return;

    const int tid = threadIdx.x;
    const int wid = tid >> 5;
    const int lid = tid & 31;
    const int wm  = wid & 1;       // 2 M-tiles of 64
    const int wn  = wid >> 1;      // 4 N-tiles of 32

    const int e  = g_te[slot];
    const int m0 = g_tm0[slot];
    const int m1 = g_tm1[slot];
    constexpr int KTOT   = G1 ? D_IN : H_FF;
    constexpr int KITERS = KTOT / BK;

    const __half* __restrict__ A  = G1 ? g_xh : g_act;
    const __half* __restrict__ Bw = G1 ? g_wup : g_wdn;

    const uint32_t sb = smem_u32(smem);

    // ---- cp.async source pointers / swizzled dst offsets (4 A-chunks + 4 B-chunks per thread)
    const __half* a_src[4]; uint32_t a_dst[4];
    const __half* b_src[4]; uint32_t b_dst[4];
    #pragma unroll
    for (int i = 0; i < 4; i++) {
        int idx = tid + i * 256;               // 0..1023
        int row = idx >> 3, ch = idx & 7;      // 128 rows x 8 chunks(16B)
        uint32_t sw = row * 128 + ((ch ^ (row & 7)) << 4);
        a_dst[i] = sw;
        b_dst[i] = A_BYTES + sw;
        a_src[i] = A + (size_t)(m0 + row) * KTOT + ch * 8;
        size_t grow;
        if (G1) {
            int h = blockIdx.y * 64 + (row >> 1);
            grow = (size_t)e * (2 * H_FF) + ((row & 1) ? (size_t)(H_FF + h) : (size_t)h);
        } else {
            grow = (size_t)e * D_IN + (size_t)(blockIdx.y * 128 + row);
        }
        b_src[i] = Bw + grow * KTOT + ch * 8;
    }

    auto load_stage = [&](int s, int kc) {
        uint32_t base = sb + s * STAGE_BYTES;
        int koff = kc * BK;
        #pragma unroll
        for (int i = 0; i < 4; i++) cp_async16(base + a_dst[i], a_src[i] + koff);
        #pragma unroll
        for (int i = 0; i < 4; i++) cp_async16(base + b_dst[i], b_src[i] + koff);
    };

    // ---- ldmatrix per-lane address pieces
    const int lrx = lid & 7;
    uint32_t a_rowoff[4], b_rowoff[2];
    #pragma unroll
    for (int mb = 0; mb < 4; mb++)
        a_rowoff[mb] = (uint32_t)(wm * 64 + mb * 16 + (lid & 15)) * 128;
    #pragma unroll
    for (int nb2 = 0; nb2 < 2; nb2++)
        b_rowoff[nb2] = A_BYTES + (uint32_t)(wn * 32 + nb2 * 16 + ((lid >> 4) << 3) + (lid & 7)) * 128;
    const int ahi = lid >> 4;            // A chunk hi bit
    const int bhi = (lid >> 3) & 1;      // B chunk hi bit

    float c[4][4][4];
    #pragma unroll
    for (int mb = 0; mb < 4; mb++)
        #pragma unroll
        for (int nb = 0; nb < 4; nb++)
            #pragma unroll
            for (int j = 0; j < 4; j++) c[mb][nb][j] = 0.f;

    // ---- prologue
    load_stage(0, 0); cp_commit();
    load_stage(1, 1); cp_commit();

    for (int kt = 0; kt < KITERS; kt++) {
        cp_wait1();
        __syncthreads();
        if (kt + 2 < KITERS) load_stage((kt + 2) % NSTAGES, kt + 2);
        cp_commit();

        const uint32_t stg = sb + (kt % NSTAGES) * STAGE_BYTES;
        #pragma unroll
        for (int ks = 0; ks < 4; ks++) {
            uint32_t a[4][4], b[2][4];
            #pragma unroll
            for (int mb = 0; mb < 4; mb++)
                ldsm4(a[mb], stg + a_rowoff[mb] + (uint32_t)(((ks * 2 + ahi) ^ lrx) << 4));
            #pragma unroll
            for (int nb2 = 0; nb2 < 2; nb2++)
                ldsm4(b[nb2], stg + b_rowoff[nb2] + (uint32_t)(((ks * 2 + bhi) ^ lrx) << 4));
            #pragma unroll
            for (int mb = 0; mb < 4; mb++) {
                #pragma unroll
                for (int nb = 0; nb < 4; nb++)
                    mma16816(c[mb][nb], a[mb], b[nb >> 1][(nb & 1) * 2], b[nb >> 1][(nb & 1) * 2 + 1]);
            }
        }
        __syncthreads();
    }

    // ---- epilogue
    if (G1) {
        // stage SwiGLU halfs to smem [128][72 halfs stride] then coalesced copy out
        __half* acts = (__half*)smem;
        const int n0h = blockIdx.y * 64;
        #pragma unroll
        for (int mb = 0; mb < 4; mb++) {
            #pragma unroll
            for (int nb = 0; nb < 4; nb++) {
                int hl = wn * 16 + nb * 4 + (lid & 3);
                int r0 = wm * 64 + mb * 16 + (lid >> 2);
                float g0 = c[mb][nb][0], u0 = c[mb][nb][1];
                float g1 = c[mb][nb][2], u1 = c[mb][nb][3];
                float v0 = u0 * g0 / (1.f + __expf(-g0));
                float v1 = u1 * g1 / (1.f + __expf(-g1));
                acts[r0 * 72 + hl]       = __float2half_rn(v0);
                acts[(r0 + 8) * 72 + hl] = __float2half_rn(v1);
            }
        }
        __syncthreads();
        for (int idx = tid; idx < 128 * 8; idx += 256) {
            int row = idx >> 3, q = idx & 7;
            if (m0 + row < m1) {
                uint4 v = *(const uint4*)((const char*)smem + row * 144 + q * 16);
                *(uint4*)(g_act + (size_t)(m0 + row) * H_FF + n0h + q * 8) = v;
            }
        }
    } else {
        const int n0 = blockIdx.y * 128;
        #pragma unroll
        for (int mb = 0; mb < 4; mb++) {
            int r0 = m0 + wm * 64 + mb * 16 + (lid >> 2);
            int r1 = r0 + 8;
            bool v0 = r0 < m1, v1 = r1 < m1;
            int tk0 = 0, tk1 = 0; float w0 = 0.f, w1 = 0.f;
            if (v0) { tk0 = g_rtok[r0]; w0 = g_rw[r0]; }
            if (v1) { tk1 = g_rtok[r1]; w1 = g_rw[r1]; }
            float* p0 = out + (size_t)tk0 * D_IN;
            float* p1 = out + (size_t)tk1 * D_IN;
            #pragma unroll
            for (int nb = 0; nb < 4; nb++) {
                int col = n0 + wn * 32 + nb * 8 + (lid & 3) * 2;
                if (v0) {
                    atomicAdd(p0 + col,     w0 * c[mb][nb][0]);
                    atomicAdd(p0 + col + 1, w0 * c[mb][nb][1]);
                }
                if (v1) {
                    atomicAdd(p1 + col,     w1 * c[mb][nb][2]);
                    atomicAdd(p1 + col + 1, w1 * c[mb][nb][3]);
                }
            }
        }
    }
}

// ---------------- launch ----------------
extern "C" void kernel_launch(void* const* d_in, const int* in_sizes, int n_in,
                              void* d_out, int out_size) {
    const float* x   = (const float*)d_in[0];   // [8192, 2048]
    const float* tw  = (const float*)d_in[1];   // [8192, 2]
    const float* wup = (const float*)d_in[2];   // [8, 11264, 2048]
    const float* wdn = (const float*)d_in[3];   // [8, 2048, 5632]
    const int*   ids = (const int*)d_in[4];     // [8192, 2]
    float* out = (float*)d_out;                 // [8192, 2048]

    cudaFuncSetAttribute(k_gemm<true>,  cudaFuncAttributeMaxDynamicSharedMemorySize, SMEM_TOTAL);
    cudaFuncSetAttribute(k_gemm<false>, cudaFuncAttributeMaxDynamicSharedMemorySize, SMEM_TOTAL);

    k_route_init<<<1, 32>>>();
    k_count<<<PAIRS / 256, 256>>>(ids);
    k_offsets<<<1, 1>>>();
    k_scatter<<<PAIRS, 256>>>(x, tw, ids);
    k_convert<<<2048, 256>>>(wup, 0);
    k_convert<<<2048, 256>>>(wdn, 1);
    k_zero<<<2048, 256>>>(out);
    k_gemm<true ><<<dim3(MAX_TILES, H_FF / 64), GEMM_THREADS, SMEM_TOTAL>>>(nullptr);
    k_gemm<false><<<dim3(MAX_TILES, D_IN / 128), GEMM_THREADS, SMEM_TOTAL>>>(out);
}

// round 4
// speedup vs baseline: 1.1689x; 1.1689x over previous
#include <cuda_runtime.h>
#include <cuda_fp16.h>
#include <cstdint>
#include <cstddef>

// ---------------- problem constants ----------------
#define NE    8
#define D_IN  2048
#define H_FF  5632
#define T_TOK 8192
#define PAIRS 16384
#define XROWS (PAIRS + 128)      // padded so GEMM tiles never read OOB

// ---------------- GEMM tiling ----------------
#define BM 128
#define BN 256
#define BK 64
#define MAX_TILES 136            // sum_e ceil(c_e/128) <= 128 + 8
#define GEMM_THREADS 512
#define NSTAGES 3
#define A_BYTES (BM * BK * 2)    // 16384
#define B_BYTES (BN * BK * 2)    // 32768
#define STAGE_BYTES (A_BYTES + B_BYTES)       // 49152
#define SMEM_TOTAL (NSTAGES * STAGE_BYTES)    // 147456

// ---------------- device scratch (static globals; no allocation) ----------------
__device__ __half g_wup[(size_t)NE * 2 * H_FF * D_IN];   // fp16 gate+up weights
__device__ __half g_wdn[(size_t)NE * D_IN * H_FF];       // fp16 down weights
__device__ __half g_xh [(size_t)XROWS * D_IN];           // gathered fp16 inputs (sorted by expert)
__device__ __half g_act[(size_t)XROWS * H_FF];           // SwiGLU activations
__device__ int   g_cnt[NE];
__device__ int   g_cur[NE];
__device__ int   g_off[NE];
__device__ int   g_rtok[PAIRS];
__device__ float g_rw  [PAIRS];
__device__ int   g_te [MAX_TILES];
__device__ int   g_tm0[MAX_TILES];
__device__ int   g_tm1[MAX_TILES];
__device__ int   g_ntiles;

// ---------------- PTX helpers ----------------
__device__ __forceinline__ uint32_t smem_u32(const void* p) {
    uint32_t a;
    asm("{ .reg .u64 t; cvta.to.shared.u64 t, %1; cvt.u32.u64 %0, t; }" : "=r"(a) : "l"(p));
    return a;
}
__device__ __forceinline__ void cp_async16(uint32_t dst, const void* src) {
    asm volatile("cp.async.cg.shared.global [%0], [%1], 16;" :: "r"(dst), "l"(src));
}
__device__ __forceinline__ void cp_commit() { asm volatile("cp.async.commit_group;" ::: "memory"); }
__device__ __forceinline__ void cp_wait1()  { asm volatile("cp.async.wait_group 1;" ::: "memory"); }

__device__ __forceinline__ void ldsm4(uint32_t* r, uint32_t addr) {
    asm volatile("ldmatrix.sync.aligned.m8n8.x4.shared.b16 {%0,%1,%2,%3}, [%4];"
                 : "=r"(r[0]), "=r"(r[1]), "=r"(r[2]), "=r"(r[3]) : "r"(addr));
}
__device__ __forceinline__ void mma16816(float* c, const uint32_t* a, uint32_t b0, uint32_t b1) {
    asm volatile(
        "mma.sync.aligned.m16n8k16.row.col.f32.f16.f16.f32 "
        "{%0,%1,%2,%3}, {%4,%5,%6,%7}, {%8,%9}, {%0,%1,%2,%3};"
        : "+f"(c[0]), "+f"(c[1]), "+f"(c[2]), "+f"(c[3])
        : "r"(a[0]), "r"(a[1]), "r"(a[2]), "r"(a[3]), "r"(b0), "r"(b1));
}

// ---------------- small kernels ----------------
// launch #1: zero output + routing state
__global__ void k_init(float* __restrict__ out) {
    if (blockIdx.x == 0 && threadIdx.x < NE) {
        g_cnt[threadIdx.x] = 0;
        g_cur[threadIdx.x] = 0;
    }
    size_t n4 = ((size_t)T_TOK * D_IN) >> 2;
    float4 z = make_float4(0.f, 0.f, 0.f, 0.f);
    size_t stride = (size_t)gridDim.x * blockDim.x;
    for (size_t i = (size_t)blockIdx.x * blockDim.x + threadIdx.x; i < n4; i += stride)
        ((float4*)out)[i] = z;
}
// launch #2
__global__ void k_count(const int* __restrict__ ids) {
    int p = blockIdx.x * blockDim.x + threadIdx.x;
    if (p < PAIRS) atomicAdd(&g_cnt[ids[p]], 1);
}
// launch #3
__global__ void k_offsets() {
    if (threadIdx.x == 0) {
        int off = 0, slot = 0;
        for (int e = 0; e < NE; e++) {
            g_off[e] = off;
            int c = g_cnt[e];
            for (int m = 0; m < c; m += BM) {
                g_te[slot]  = e;
                g_tm0[slot] = off + m;
                g_tm1[slot] = off + ((m + BM < c) ? (m + BM) : c);
                slot++;
            }
            off += c;
        }
        g_ntiles = slot;
    }
}
// launch #4
__global__ void k_scatter(const float* __restrict__ x, const float* __restrict__ tw,
                          const int* __restrict__ ids) {
    int p = blockIdx.x;            // pair index
    int t = p >> 1;
    __shared__ int spos;
    if (threadIdx.x == 0) {
        int e   = ids[p];
        int pos = g_off[e] + atomicAdd(&g_cur[e], 1);
        g_rtok[pos] = t;
        g_rw[pos]   = tw[p];
        spos = pos;
    }
    __syncthreads();
    int pos = spos;
    const float4* src = (const float4*)(x + (size_t)t * D_IN);
    uint2* dst = (uint2*)(g_xh + (size_t)pos * D_IN);
    for (int i = threadIdx.x; i < D_IN / 4; i += 256) {
        float4 v = src[i];
        __half2 a = __floats2half2_rn(v.x, v.y);
        __half2 b = __floats2half2_rn(v.z, v.w);
        uint2 o;
        o.x = *reinterpret_cast<uint32_t*>(&a);
        o.y = *reinterpret_cast<uint32_t*>(&b);
        dst[i] = o;
    }
}
// launch #5: fp32 -> fp16 for both weight tensors
__global__ void k_convert(const float* __restrict__ sup, const float* __restrict__ sdn) {
    const size_t nup4 = ((size_t)NE * 2 * H_FF * D_IN) >> 2;
    const size_t ndn4 = ((size_t)NE * D_IN * H_FF) >> 2;
    size_t stride = (size_t)gridDim.x * blockDim.x;
    size_t i0 = (size_t)blockIdx.x * blockDim.x + threadIdx.x;
    for (size_t i = i0; i < nup4 + ndn4; i += stride) {
        const float4* s = (i < nup4) ? ((const float4*)sup + i) : ((const float4*)sdn + (i - nup4));
        uint2* d = (i < nup4) ? ((uint2*)g_wup + i) : ((uint2*)g_wdn + (i - nup4));
        float4 v = *s;
        __half2 a = __floats2half2_rn(v.x, v.y);
        __half2 b = __floats2half2_rn(v.z, v.w);
        uint2 o;
        o.x = *reinterpret_cast<uint32_t*>(&a);
        o.y = *reinterpret_cast<uint32_t*>(&b);
        *d = o;
    }
}

// ---------------- grouped GEMM (mma.sync m16n8k16, 3-stage cp.async, SW128 smem) ----------------
// 512 threads, CTA tile 128x256x64, warp tile 64x32 (wm in {0,1}, wn in {0..7}).
// G1: B smem row r (0..255): h = y*128 + (r>>1); weight row (r even ? h : H_FF+h) of g_wup[e].
//     Lane accum pair (c0,c1)/(c2,c3) = (gate,up) of same h -> SwiGLU -> g_act.
// G2: B = g_wdn[e] rows y*256..+255 -> w * y atomicAdd into out.
template<bool G1>
__global__ void __launch_bounds__(GEMM_THREADS, 1) k_gemm(float* __restrict__ out) {
    extern __shared__ char smem[];
    const int slot = blockIdx.x;
    if (slot >= g_ntiles) return;

    const int tid = threadIdx.x;
    const int wid = tid >> 5;
    const int lid = tid & 31;
    const int wm  = wid & 1;       // 2 M-tiles of 64
    const int wn  = wid >> 1;      // 8 N-tiles of 32

    const int e  = g_te[slot];
    const int m0 = g_tm0[slot];
    const int m1 = g_tm1[slot];
    constexpr int KTOT   = G1 ? D_IN : H_FF;
    constexpr int KITERS = KTOT / BK;

    const __half* __restrict__ A  = G1 ? g_xh : g_act;
    const __half* __restrict__ Bw = G1 ? g_wup : g_wdn;

    const uint32_t sb = smem_u32(smem);

    // ---- cp.async: 2 A-chunks + 4 B-chunks per thread (16B each)
    const __half* a_src[2]; uint32_t a_dst[2];
    #pragma unroll
    for (int i = 0; i < 2; i++) {
        int idx = tid + i * 512;               // 0..1023
        int row = idx >> 3, ch = idx & 7;      // 128 rows x 8 chunks
        uint32_t sw = row * 128 + ((ch ^ (row & 7)) << 4);
        a_dst[i] = sw;
        a_src[i] = A + (size_t)(m0 + row) * KTOT + ch * 8;
    }
    const __half* b_src[4]; uint32_t b_dst[4];
    #pragma unroll
    for (int i = 0; i < 4; i++) {
        int idx = tid + i * 512;               // 0..2047
        int row = idx >> 3, ch = idx & 7;      // 256 rows x 8 chunks
        uint32_t sw = row * 128 + ((ch ^ (row & 7)) << 4);
        b_dst[i] = A_BYTES + sw;
        size_t grow;
        if (G1) {
            int h = blockIdx.y * 128 + (row >> 1);
            grow = (size_t)e * (2 * H_FF) + ((row & 1) ? (size_t)(H_FF + h) : (size_t)h);
        } else {
            grow = (size_t)e * D_IN + (size_t)(blockIdx.y * 256 + row);
        }
        b_src[i] = Bw + grow * KTOT + ch * 8;
    }

    auto load_stage = [&](int s, int kc) {
        uint32_t base = sb + s * STAGE_BYTES;
        int koff = kc * BK;
        #pragma unroll
        for (int i = 0; i < 2; i++) cp_async16(base + a_dst[i], a_src[i] + koff);
        #pragma unroll
        for (int i = 0; i < 4; i++) cp_async16(base + b_dst[i], b_src[i] + koff);
    };

    // ---- ldmatrix per-lane address pieces
    const int lrx = lid & 7;
    uint32_t a_rowoff[4], b_rowoff[2];
    #pragma unroll
    for (int mb = 0; mb < 4; mb++)
        a_rowoff[mb] = (uint32_t)(wm * 64 + mb * 16 + (lid & 15)) * 128;
    #pragma unroll
    for (int nb2 = 0; nb2 < 2; nb2++)
        b_rowoff[nb2] = A_BYTES + (uint32_t)(wn * 32 + nb2 * 16 + ((lid >> 4) << 3) + (lid & 7)) * 128;
    const int ahi = lid >> 4;            // A chunk hi bit
    const int bhi = (lid >> 3) & 1;      // B chunk hi bit

    float c[4][4][4];
    #pragma unroll
    for (int mb = 0; mb < 4; mb++)
        #pragma unroll
        for (int nb = 0; nb < 4; nb++)
            #pragma unroll
            for (int j = 0; j < 4; j++) c[mb][nb][j] = 0.f;

    // ---- prologue
    load_stage(0, 0); cp_commit();
    load_stage(1, 1); cp_commit();

    for (int kt = 0; kt < KITERS; kt++) {
        cp_wait1();
        __syncthreads();
        if (kt + 2 < KITERS) load_stage((kt + 2) % NSTAGES, kt + 2);
        cp_commit();

        const uint32_t stg = sb + (kt % NSTAGES) * STAGE_BYTES;
        #pragma unroll
        for (int ks = 0; ks < 4; ks++) {
            uint32_t a[4][4], b[2][4];
            #pragma unroll
            for (int mb = 0; mb < 4; mb++)
                ldsm4(a[mb], stg + a_rowoff[mb] + (uint32_t)(((ks * 2 + ahi) ^ lrx) << 4));
            #pragma unroll
            for (int nb2 = 0; nb2 < 2; nb2++)
                ldsm4(b[nb2], stg + b_rowoff[nb2] + (uint32_t)(((ks * 2 + bhi) ^ lrx) << 4));
            #pragma unroll
            for (int mb = 0; mb < 4; mb++) {
                #pragma unroll
                for (int nb = 0; nb < 4; nb++)
                    mma16816(c[mb][nb], a[mb], b[nb >> 1][(nb & 1) * 2], b[nb >> 1][(nb & 1) * 2 + 1]);
            }
        }
        __syncthreads();
    }

    // ---- epilogue
    if (G1) {
        // SwiGLU -> stage fp16 to smem [128 rows][128 halfs, stride 136] -> coalesced copy out
        __half* acts = (__half*)smem;
        const int n0h = blockIdx.y * 128;
        #pragma unroll
        for (int mb = 0; mb < 4; mb++) {
            #pragma unroll
            for (int nb = 0; nb < 4; nb++) {
                int hl = wn * 16 + nb * 4 + (lid & 3);
                int r0 = wm * 64 + mb * 16 + (lid >> 2);
                float g0 = c[mb][nb][0], u0 = c[mb][nb][1];
                float g1 = c[mb][nb][2], u1 = c[mb][nb][3];
                float v0 = u0 * g0 / (1.f + __expf(-g0));
                float v1 = u1 * g1 / (1.f + __expf(-g1));
                acts[r0 * 136 + hl]       = __float2half_rn(v0);
                acts[(r0 + 8) * 136 + hl] = __float2half_rn(v1);
            }
        }
        __syncthreads();
        for (int idx = tid; idx < 128 * 16; idx += GEMM_THREADS) {
            int row = idx >> 4, q = idx & 15;
            if (m0 + row < m1) {
                uint4 v = *(const uint4*)((const char*)smem + row * 272 + q * 16);
                *(uint4*)(g_act + (size_t)(m0 + row) * H_FF + n0h + q * 8) = v;
            }
        }
    } else {
        const int n0 = blockIdx.y * 256;
        #pragma unroll
        for (int mb = 0; mb < 4; mb++) {
            int r0 = m0 + wm * 64 + mb * 16 + (lid >> 2);
            int r1 = r0 + 8;
            bool v0 = r0 < m1, v1 = r1 < m1;
            int tk0 = 0, tk1 = 0; float w0 = 0.f, w1 = 0.f;
            if (v0) { tk0 = g_rtok[r0]; w0 = g_rw[r0]; }
            if (v1) { tk1 = g_rtok[r1]; w1 = g_rw[r1]; }
            float* p0 = out + (size_t)tk0 * D_IN;
            float* p1 = out + (size_t)tk1 * D_IN;
            #pragma unroll
            for (int nb = 0; nb < 4; nb++) {
                int col = n0 + wn * 32 + nb * 8 + (lid & 3) * 2;
                if (v0) {
                    atomicAdd(p0 + col,     w0 * c[mb][nb][0]);
                    atomicAdd(p0 + col + 1, w0 * c[mb][nb][1]);
                }
                if (v1) {
                    atomicAdd(p1 + col,     w1 * c[mb][nb][2]);
                    atomicAdd(p1 + col + 1, w1 * c[mb][nb][3]);
                }
            }
        }
    }
}

// ---------------- launch ----------------
extern "C" void kernel_launch(void* const* d_in, const int* in_sizes, int n_in,
                              void* d_out, int out_size) {
    const float* x   = (const float*)d_in[0];   // [8192, 2048]
    const float* tw  = (const float*)d_in[1];   // [8192, 2]
    const float* wup = (const float*)d_in[2];   // [8, 11264, 2048]
    const float* wdn = (const float*)d_in[3];   // [8, 2048, 5632]
    const int*   ids = (const int*)d_in[4];     // [8192, 2]
    float* out = (float*)d_out;                 // [8192, 2048]

    cudaFuncSetAttribute(k_gemm<true>,  cudaFuncAttributeMaxDynamicSharedMemorySize, SMEM_TOTAL);
    cudaFuncSetAttribute(k_gemm<false>, cudaFuncAttributeMaxDynamicSharedMemorySize, SMEM_TOTAL);

    k_init<<<1024, 256>>>(out);                       // #1
    k_count<<<PAIRS / 256, 256>>>(ids);               // #2
    k_offsets<<<1, 1>>>();                            // #3
    k_scatter<<<PAIRS, 256>>>(x, tw, ids);            // #4
    k_convert<<<4096, 256>>>(wup, wdn);               // #5
    k_gemm<true ><<<dim3(MAX_TILES, H_FF / 128), GEMM_THREADS, SMEM_TOTAL>>>(nullptr);  // #6 (profiled)
    k_gemm<false><<<dim3(MAX_TILES, D_IN / 256), GEMM_THREADS, SMEM_TOTAL>>>(out);      // #7
}

// round 5
// speedup vs baseline: 1.1719x; 1.0026x over previous
#include <cuda_runtime.h>
#include <cuda_fp16.h>
#include <cstdint>
#include <cstddef>

// ---------------- problem constants ----------------
#define NE    8
#define D_IN  2048
#define H_FF  5632
#define T_TOK 8192
#define PAIRS 16384
#define XROWS (PAIRS + 128)      // padded so GEMM tiles never read OOB

// ---------------- GEMM tiling ----------------
#define BM 128
#define BN 256
#define BK 64
#define MAX_TILES 136            // sum_e ceil(c_e/128) <= 128 + 8
#define GEMM_THREADS 512
#define NSTAGES 4
#define A_BYTES (BM * BK * 2)    // 16384
#define B_BYTES (BN * BK * 2)    // 32768
#define STAGE_BYTES (A_BYTES + B_BYTES)       // 49152
#define SMEM_TOTAL (NSTAGES * STAGE_BYTES)    // 196608

// ---------------- device scratch (static globals; no allocation) ----------------
__device__ __half g_wup[(size_t)NE * 2 * H_FF * D_IN];   // fp16 gate+up weights
__device__ __half g_wdn[(size_t)NE * D_IN * H_FF];       // fp16 down weights
__device__ __half g_xh [(size_t)XROWS * D_IN];           // gathered fp16 inputs (sorted by expert)
__device__ __half g_act[(size_t)XROWS * H_FF];           // SwiGLU activations
__device__ int   g_cur[NE];
__device__ int   g_off[NE];
__device__ int   g_rtok[PAIRS];
__device__ float g_rw  [PAIRS];
__device__ int   g_te [MAX_TILES];
__device__ int   g_tm0[MAX_TILES];
__device__ int   g_tm1[MAX_TILES];
__device__ int   g_ntiles;

// ---------------- PTX helpers ----------------
__device__ __forceinline__ uint32_t smem_u32(const void* p) {
    uint32_t a;
    asm("{ .reg .u64 t; cvta.to.shared.u64 t, %1; cvt.u32.u64 %0, t; }" : "=r"(a) : "l"(p));
    return a;
}
__device__ __forceinline__ void cp_async16(uint32_t dst, const void* src) {
    asm volatile("cp.async.cg.shared.global [%0], [%1], 16;" :: "r"(dst), "l"(src));
}
__device__ __forceinline__ void cp_commit() { asm volatile("cp.async.commit_group;" ::: "memory"); }
__device__ __forceinline__ void cp_wait2()  { asm volatile("cp.async.wait_group 2;" ::: "memory"); }

__device__ __forceinline__ void ldsm4(uint32_t* r, uint32_t addr) {
    asm volatile("ldmatrix.sync.aligned.m8n8.x4.shared.b16 {%0,%1,%2,%3}, [%4];"
                 : "=r"(r[0]), "=r"(r[1]), "=r"(r[2]), "=r"(r[3]) : "r"(addr));
}
__device__ __forceinline__ void mma16816(float* c, const uint32_t* a, uint32_t b0, uint32_t b1) {
    asm volatile(
        "mma.sync.aligned.m16n8k16.row.col.f32.f16.f16.f32 "
        "{%0,%1,%2,%3}, {%4,%5,%6,%7}, {%8,%9}, {%0,%1,%2,%3};"
        : "+f"(c[0]), "+f"(c[1]), "+f"(c[2]), "+f"(c[3])
        : "r"(a[0]), "r"(a[1]), "r"(a[2]), "r"(a[3]), "r"(b0), "r"(b1));
}
__device__ __forceinline__ void redg_v2(float* p, float a, float b) {
    asm volatile("red.global.add.v2.f32 [%0], {%1, %2};" :: "l"(p), "f"(a), "f"(b) : "memory");
}

// ---------------- launch #1: zero output + routing cursors ----------------
__global__ void k_init(float* __restrict__ out) {
    if (blockIdx.x == 0 && threadIdx.x < NE) g_cur[threadIdx.x] = 0;
    size_t n4 = ((size_t)T_TOK * D_IN) >> 2;
    float4 z = make_float4(0.f, 0.f, 0.f, 0.f);
    size_t stride = (size_t)gridDim.x * blockDim.x;
    for (size_t i = (size_t)blockIdx.x * blockDim.x + threadIdx.x; i < n4; i += stride)
        ((float4*)out)[i] = z;
}

// ---------------- launch #2: single-block histogram + offsets + tile table ----------------
__global__ void k_hist(const int* __restrict__ ids) {
    __shared__ int h[NE];
    int tid = threadIdx.x;
    if (tid < NE) h[tid] = 0;
    __syncthreads();
    for (int i = tid; i < PAIRS; i += 1024) atomicAdd(&h[ids[i]], 1);
    __syncthreads();
    if (tid == 0) {
        int off = 0, slot = 0;
        for (int e = 0; e < NE; e++) {
            g_off[e] = off;
            int c = h[e];
            for (int m = 0; m < c; m += BM) {
                g_te[slot]  = e;
                g_tm0[slot] = off + m;
                g_tm1[slot] = off + ((m + BM < c) ? (m + BM) : c);
                slot++;
            }
            off += c;
        }
        g_ntiles = slot;
    }
}

// ---------------- launch #3: fused scatter (blocks < PAIRS) + weight convert ----------------
#define CONV_BLOCKS 4096
__global__ void k_prep(const float* __restrict__ x, const float* __restrict__ tw,
                       const int* __restrict__ ids,
                       const float* __restrict__ sup, const float* __restrict__ sdn) {
    if (blockIdx.x < PAIRS) {
        int p = blockIdx.x;            // pair index
        int t = p >> 1;
        __shared__ int spos;
        if (threadIdx.x == 0) {
            int e   = ids[p];
            int pos = g_off[e] + atomicAdd(&g_cur[e], 1);
            g_rtok[pos] = t;
            g_rw[pos]   = tw[p];
            spos = pos;
        }
        __syncthreads();
        int pos = spos;
        const float4* src = (const float4*)(x + (size_t)t * D_IN);
        uint2* dst = (uint2*)(g_xh + (size_t)pos * D_IN);
        for (int i = threadIdx.x; i < D_IN / 4; i += 256) {
            float4 v = src[i];
            __half2 a = __floats2half2_rn(v.x, v.y);
            __half2 b = __floats2half2_rn(v.z, v.w);
            uint2 o;
            o.x = *reinterpret_cast<uint32_t*>(&a);
            o.y = *reinterpret_cast<uint32_t*>(&b);
            dst[i] = o;
        }
    } else {
        const size_t nup4 = ((size_t)NE * 2 * H_FF * D_IN) >> 2;
        const size_t ndn4 = ((size_t)NE * D_IN * H_FF) >> 2;
        size_t stride = (size_t)CONV_BLOCKS * 256;
        size_t i0 = (size_t)(blockIdx.x - PAIRS) * 256 + threadIdx.x;
        for (size_t i = i0; i < nup4 + ndn4; i += stride) {
            const float4* s = (i < nup4) ? ((const float4*)sup + i) : ((const float4*)sdn + (i - nup4));
            uint2* d = (i < nup4) ? ((uint2*)g_wup + i) : ((uint2*)g_wdn + (i - nup4));
            float4 v = *s;
            __half2 a = __floats2half2_rn(v.x, v.y);
            __half2 b = __floats2half2_rn(v.z, v.w);
            uint2 o;
            o.x = *reinterpret_cast<uint32_t*>(&a);
            o.y = *reinterpret_cast<uint32_t*>(&b);
            *d = o;
        }
    }
}

// ---------------- grouped GEMM (mma.sync m16n8k16, 4-stage cp.async, SW128 smem) ----------------
// 512 threads, CTA tile 128x256x64, warp tile 64x32 (wm in {0,1}, wn in {0..7}).
// G1: B smem row r (0..255): h = y*128 + (r>>1); weight row (r even ? h : H_FF+h) of g_wup[e].
//     Lane accum pairs = (gate,up) of same h -> SwiGLU -> g_act.
// G2: B = g_wdn[e] rows y*256..+255 -> w * y red.v2 into out.
template<bool G1>
__global__ void __launch_bounds__(GEMM_THREADS, 1) k_gemm(float* __restrict__ out) {
    extern __shared__ char smem[];
    const int slot = blockIdx.x;
    if (slot >= g_ntiles) return;

    const int tid = threadIdx.x;
    const int wid = tid >> 5;
    const int lid = tid & 31;
    const int wm  = wid & 1;       // 2 M-tiles of 64
    const int wn  = wid >> 1;      // 8 N-tiles of 32

    const int e  = g_te[slot];
    const int m0 = g_tm0[slot];
    const int m1 = g_tm1[slot];
    constexpr int KTOT   = G1 ? D_IN : H_FF;
    constexpr int KITERS = KTOT / BK;

    const __half* __restrict__ A  = G1 ? g_xh : g_act;
    const __half* __restrict__ Bw = G1 ? g_wup : g_wdn;

    const uint32_t sb = smem_u32(smem);

    // ---- cp.async: 2 A-chunks + 4 B-chunks per thread (16B each)
    const __half* a_src[2]; uint32_t a_dst[2];
    #pragma unroll
    for (int i = 0; i < 2; i++) {
        int idx = tid + i * 512;               // 0..1023
        int row = idx >> 3, ch = idx & 7;      // 128 rows x 8 chunks
        uint32_t sw = row * 128 + ((ch ^ (row & 7)) << 4);
        a_dst[i] = sw;
        a_src[i] = A + (size_t)(m0 + row) * KTOT + ch * 8;
    }
    const __half* b_src[4]; uint32_t b_dst[4];
    #pragma unroll
    for (int i = 0; i < 4; i++) {
        int idx = tid + i * 512;               // 0..2047
        int row = idx >> 3, ch = idx & 7;      // 256 rows x 8 chunks
        uint32_t sw = row * 128 + ((ch ^ (row & 7)) << 4);
        b_dst[i] = A_BYTES + sw;
        size_t grow;
        if (G1) {
            int h = blockIdx.y * 128 + (row >> 1);
            grow = (size_t)e * (2 * H_FF) + ((row & 1) ? (size_t)(H_FF + h) : (size_t)h);
        } else {
            grow = (size_t)e * D_IN + (size_t)(blockIdx.y * 256 + row);
        }
        b_src[i] = Bw + grow * KTOT + ch * 8;
    }

    auto load_stage = [&](int s, int kc) {
        uint32_t base = sb + s * STAGE_BYTES;
        int koff = kc * BK;
        #pragma unroll
        for (int i = 0; i < 2; i++) cp_async16(base + a_dst[i], a_src[i] + koff);
        #pragma unroll
        for (int i = 0; i < 4; i++) cp_async16(base + b_dst[i], b_src[i] + koff);
    };

    // ---- ldmatrix per-lane address pieces
    const int lrx = lid & 7;
    uint32_t a_rowoff[4], b_rowoff[2];
    #pragma unroll
    for (int mb = 0; mb < 4; mb++)
        a_rowoff[mb] = (uint32_t)(wm * 64 + mb * 16 + (lid & 15)) * 128;
    #pragma unroll
    for (int nb2 = 0; nb2 < 2; nb2++)
        b_rowoff[nb2] = A_BYTES + (uint32_t)(wn * 32 + nb2 * 16 + ((lid >> 4) << 3) + (lid & 7)) * 128;
    const int ahi = lid >> 4;            // A chunk hi bit
    const int bhi = (lid >> 3) & 1;      // B chunk hi bit

    float c[4][4][4];
    #pragma unroll
    for (int mb = 0; mb < 4; mb++)
        #pragma unroll
        for (int nb = 0; nb < 4; nb++)
            #pragma unroll
            for (int j = 0; j < 4; j++) c[mb][nb][j] = 0.f;

    // ---- prologue: 3 stages in flight
    load_stage(0, 0); cp_commit();
    load_stage(1, 1); cp_commit();
    load_stage(2, 2); cp_commit();

    for (int kt = 0; kt < KITERS; kt++) {
        cp_wait2();
        __syncthreads();
        if (kt + 3 < KITERS) load_stage((kt + 3) & (NSTAGES - 1), kt + 3);
        cp_commit();

        const uint32_t stg = sb + (kt & (NSTAGES - 1)) * STAGE_BYTES;
        #pragma unroll
        for (int ks = 0; ks < 4; ks++) {
            uint32_t a[4][4], b[2][4];
            #pragma unroll
            for (int mb = 0; mb < 4; mb++)
                ldsm4(a[mb], stg + a_rowoff[mb] + (uint32_t)(((ks * 2 + ahi) ^ lrx) << 4));
            #pragma unroll
            for (int nb2 = 0; nb2 < 2; nb2++)
                ldsm4(b[nb2], stg + b_rowoff[nb2] + (uint32_t)(((ks * 2 + bhi) ^ lrx) << 4));
            #pragma unroll
            for (int mb = 0; mb < 4; mb++) {
                #pragma unroll
                for (int nb = 0; nb < 4; nb++)
                    mma16816(c[mb][nb], a[mb], b[nb >> 1][(nb & 1) * 2], b[nb >> 1][(nb & 1) * 2 + 1]);
            }
        }
    }
    __syncthreads();   // protect smem reuse by epilogue staging

    // ---- epilogue
    if (G1) {
        // SwiGLU -> stage fp16 to smem [128 rows][128 halfs, stride 136] -> coalesced copy out
        __half* acts = (__half*)smem;
        const int n0h = blockIdx.y * 128;
        #pragma unroll
        for (int mb = 0; mb < 4; mb++) {
            #pragma unroll
            for (int nb = 0; nb < 4; nb++) {
                int hl = wn * 16 + nb * 4 + (lid & 3);
                int r0 = wm * 64 + mb * 16 + (lid >> 2);
                float g0 = c[mb][nb][0], u0 = c[mb][nb][1];
                float g1 = c[mb][nb][2], u1 = c[mb][nb][3];
                float v0 = u0 * g0 / (1.f + __expf(-g0));
                float v1 = u1 * g1 / (1.f + __expf(-g1));
                acts[r0 * 136 + hl]       = __float2half_rn(v0);
                acts[(r0 + 8) * 136 + hl] = __float2half_rn(v1);
            }
        }
        __syncthreads();
        for (int idx = tid; idx < 128 * 16; idx += GEMM_THREADS) {
            int row = idx >> 4, q = idx & 15;
            if (m0 + row < m1) {
                uint4 v = *(const uint4*)((const char*)smem + row * 272 + q * 16);
                *(uint4*)(g_act + (size_t)(m0 + row) * H_FF + n0h + q * 8) = v;
            }
        }
    } else {
        const int n0 = blockIdx.y * 256;
        #pragma unroll
        for (int mb = 0; mb < 4; mb++) {
            int r0 = m0 + wm * 64 + mb * 16 + (lid >> 2);
            int r1 = r0 + 8;
            bool v0 = r0 < m1, v1 = r1 < m1;
            int tk0 = 0, tk1 = 0; float w0 = 0.f, w1 = 0.f;
            if (v0) { tk0 = g_rtok[r0]; w0 = g_rw[r0]; }
            if (v1) { tk1 = g_rtok[r1]; w1 = g_rw[r1]; }
            float* p0 = out + (size_t)tk0 * D_IN;
            float* p1 = out + (size_t)tk1 * D_IN;
            #pragma unroll
            for (int nb = 0; nb < 4; nb++) {
                int col = n0 + wn * 32 + nb * 8 + (lid & 3) * 2;
                if (v0) redg_v2(p0 + col, w0 * c[mb][nb][0], w0 * c[mb][nb][1]);
                if (v1) redg_v2(p1 + col, w1 * c[mb][nb][2], w1 * c[mb][nb][3]);
            }
        }
    }
}

// ---------------- launch ----------------
extern "C" void kernel_launch(void* const* d_in, const int* in_sizes, int n_in,
                              void* d_out, int out_size) {
    const float* x   = (const float*)d_in[0];   // [8192, 2048]
    const float* tw  = (const float*)d_in[1];   // [8192, 2]
    const float* wup = (const float*)d_in[2];   // [8, 11264, 2048]
    const float* wdn = (const float*)d_in[3];   // [8, 2048, 5632]
    const int*   ids = (const int*)d_in[4];     // [8192, 2]
    float* out = (float*)d_out;                 // [8192, 2048]

    cudaFuncSetAttribute(k_gemm<true>,  cudaFuncAttributeMaxDynamicSharedMemorySize, SMEM_TOTAL);
    cudaFuncSetAttribute(k_gemm<false>, cudaFuncAttributeMaxDynamicSharedMemorySize, SMEM_TOTAL);

    k_init<<<1024, 256>>>(out);                                 // #1
    k_hist<<<1, 1024>>>(ids);                                   // #2
    k_prep<<<PAIRS + CONV_BLOCKS, 256>>>(x, tw, ids, wup, wdn); // #3
    k_gemm<true ><<<dim3(MAX_TILES, H_FF / 128), GEMM_THREADS, SMEM_TOTAL>>>(nullptr);  // #4 (profiled)
    k_gemm<false><<<dim3(MAX_TILES, D_IN / 256), GEMM_THREADS, SMEM_TOTAL>>>(out);      // #5
}

// round 6
// speedup vs baseline: 1.2584x; 1.0738x over previous
#include <cuda_runtime.h>
#include <cuda_fp16.h>
#include <cstdint>
#include <cstddef>

// ---------------- problem constants ----------------
#define NE    8
#define D_IN  2048
#define H_FF  5632
#define T_TOK 8192
#define PAIRS 16384
#define XROWS (PAIRS + 128)      // padded so GEMM tiles never read OOB

// ---------------- GEMM tiling ----------------
#define BM 128
#define BN 256
#define BK 64
#define MAX_TILES 136            // sum_e ceil(c_e/128) <= 128 + 8
#define GEMM_THREADS 512
#define NSTAGES 4
#define A_BYTES (BM * BK * 2)    // 16384
#define B_BYTES (BN * BK * 2)    // 32768
#define STAGE_BYTES (A_BYTES + B_BYTES)       // 49152
#define SMEM_TOTAL (NSTAGES * STAGE_BYTES)    // 196608

#define G1_YTILES (H_FF / 128)   // 44
#define CONVUP_BLOCKS 3072
#define ZERO_BLOCKS 512

// ---------------- device scratch (static globals; no allocation) ----------------
__device__ __half g_wup[(size_t)NE * 2 * H_FF * D_IN];   // fp16 gate+up weights
__device__ __half g_wdn[(size_t)NE * D_IN * H_FF];       // fp16 down weights
__device__ __half g_xh [(size_t)XROWS * D_IN];           // gathered fp16 inputs (sorted by expert)
__device__ __half g_act[(size_t)XROWS * H_FF];           // SwiGLU activations
__device__ int   g_cur[NE];
__device__ int   g_off[NE];
__device__ int   g_rtok[PAIRS];
__device__ float g_rw  [PAIRS];
__device__ int   g_te [MAX_TILES];
__device__ int   g_tm0[MAX_TILES];
__device__ int   g_tm1[MAX_TILES];
__device__ int   g_ntiles;

// ---------------- PTX helpers ----------------
__device__ __forceinline__ uint32_t smem_u32(const void* p) {
    uint32_t a;
    asm("{ .reg .u64 t; cvta.to.shared.u64 t, %1; cvt.u32.u64 %0, t; }" : "=r"(a) : "l"(p));
    return a;
}
__device__ __forceinline__ void cp_async16(uint32_t dst, const void* src) {
    asm volatile("cp.async.cg.shared.global [%0], [%1], 16;" :: "r"(dst), "l"(src));
}
__device__ __forceinline__ void cp_commit() { asm volatile("cp.async.commit_group;" ::: "memory"); }
__device__ __forceinline__ void cp_wait0()  { asm volatile("cp.async.wait_group 0;" ::: "memory"); }

__device__ __forceinline__ void ldsm4(uint32_t* r, uint32_t addr) {
    asm volatile("ldmatrix.sync.aligned.m8n8.x4.shared.b16 {%0,%1,%2,%3}, [%4];"
                 : "=r"(r[0]), "=r"(r[1]), "=r"(r[2]), "=r"(r[3]) : "r"(addr));
}
__device__ __forceinline__ void mma16816(float* c, const uint32_t* a, uint32_t b0, uint32_t b1) {
    asm volatile(
        "mma.sync.aligned.m16n8k16.row.col.f32.f16.f16.f32 "
        "{%0,%1,%2,%3}, {%4,%5,%6,%7}, {%8,%9}, {%0,%1,%2,%3};"
        : "+f"(c[0]), "+f"(c[1]), "+f"(c[2]), "+f"(c[3])
        : "r"(a[0]), "r"(a[1]), "r"(a[2]), "r"(a[3]), "r"(b0), "r"(b1));
}
__device__ __forceinline__ void redg_v2(float* p, float a, float b) {
    asm volatile("red.global.add.v2.f32 [%0], {%1, %2};" :: "l"(p), "f"(a), "f"(b) : "memory");
}
__device__ __forceinline__ uint2 cvt2(float4 v) {
    __half2 a = __floats2half2_rn(v.x, v.y);
    __half2 b = __floats2half2_rn(v.z, v.w);
    uint2 o;
    o.x = *reinterpret_cast<uint32_t*>(&a);
    o.y = *reinterpret_cast<uint32_t*>(&b);
    return o;
}

// ---------------- launch #1: histogram + offsets + tile table + cursors ----------------
__global__ void k_hist(const int* __restrict__ ids) {
    __shared__ int h[NE];
    int tid = threadIdx.x;
    if (tid < NE) h[tid] = 0;
    __syncthreads();
    for (int i = tid; i < PAIRS; i += 1024) atomicAdd(&h[ids[i]], 1);
    __syncthreads();
    if (tid < NE) g_cur[tid] = 0;
    if (tid == 0) {
        int off = 0, slot = 0;
        for (int e = 0; e < NE; e++) {
            g_off[e] = off;
            int c = h[e];
            for (int m = 0; m < c; m += BM) {
                g_te[slot]  = e;
                g_tm0[slot] = off + m;
                g_tm1[slot] = off + ((m + BM < c) ? (m + BM) : c);
                slot++;
            }
            off += c;
        }
        g_ntiles = slot;
    }
}

// ---------------- launch #2: scatter + up-weight convert + zero(out) ----------------
__global__ void k_prep(const float* __restrict__ x, const float* __restrict__ tw,
                       const int* __restrict__ ids,
                       const float* __restrict__ sup, float* __restrict__ out) {
    if (blockIdx.x < PAIRS) {
        int p = blockIdx.x;            // pair index
        int t = p >> 1;
        __shared__ int spos;
        if (threadIdx.x == 0) {
            int e   = ids[p];
            int pos = g_off[e] + atomicAdd(&g_cur[e], 1);
            g_rtok[pos] = t;
            g_rw[pos]   = tw[p];
            spos = pos;
        }
        __syncthreads();
        int pos = spos;
        const float4* src = (const float4*)(x + (size_t)t * D_IN);
        uint2* dst = (uint2*)(g_xh + (size_t)pos * D_IN);
        for (int i = threadIdx.x; i < D_IN / 4; i += 256)
            dst[i] = cvt2(src[i]);
    } else if (blockIdx.x < PAIRS + CONVUP_BLOCKS) {
        const size_t nup4 = ((size_t)NE * 2 * H_FF * D_IN) >> 2;
        size_t stride = (size_t)CONVUP_BLOCKS * 256;
        for (size_t i = (size_t)(blockIdx.x - PAIRS) * 256 + threadIdx.x; i < nup4; i += stride)
            ((uint2*)g_wup)[i] = cvt2(((const float4*)sup)[i]);
    } else {
        size_t n4 = ((size_t)T_TOK * D_IN) >> 2;
        float4 z = make_float4(0.f, 0.f, 0.f, 0.f);
        size_t stride = (size_t)ZERO_BLOCKS * 256;
        for (size_t i = (size_t)(blockIdx.x - PAIRS - CONVUP_BLOCKS) * 256 + threadIdx.x; i < n4; i += stride)
            ((float4*)out)[i] = z;
    }
}

// ---------------- grouped GEMM (mma.sync m16n8k16, 4-stage cp.async, pairwise barrier) ----------------
// 512 threads, CTA tile 128x256x64, warp tile 64x32 (wm in {0,1}, wn in {0..7}).
// G1: B smem row r (0..255): h = y*128 + (r>>1); weight row (r even ? h : H_FF+h) of g_wup[e].
//     Lane accum pairs = (gate,up) of same h -> SwiGLU -> g_act. (y == G1_YTILES row: down-weight convert.)
// G2: B = g_wdn[e] rows y*256..+255 -> w * y red.v2 into out.
template<bool G1>
__global__ void __launch_bounds__(GEMM_THREADS, 1) k_gemm(float* __restrict__ out,
                                                          const float* __restrict__ sdn) {
    if (G1 && blockIdx.y == G1_YTILES) {
        // piggybacked down-weight conversion (overlaps with G1 tensor work)
        const size_t ndn4 = ((size_t)NE * D_IN * H_FF) >> 2;
        size_t stride = (size_t)gridDim.x * GEMM_THREADS;
        for (size_t i = (size_t)blockIdx.x * GEMM_THREADS + threadIdx.x; i < ndn4; i += stride)
            ((uint2*)g_wdn)[i] = cvt2(((const float4*)sdn)[i]);
        return;
    }
    extern __shared__ char smem[];
    const int slot = blockIdx.x;
    if (slot >= g_ntiles) return;

    const int tid = threadIdx.x;
    const int wid = tid >> 5;
    const int lid = tid & 31;
    const int wm  = wid & 1;       // 2 M-tiles of 64
    const int wn  = wid >> 1;      // 8 N-tiles of 32

    const int e  = g_te[slot];
    const int m0 = g_tm0[slot];
    const int m1 = g_tm1[slot];
    constexpr int KTOT   = G1 ? D_IN : H_FF;
    constexpr int KITERS = KTOT / BK;   // 32 / 88 (both even)

    const __half* __restrict__ A  = G1 ? g_xh : g_act;
    const __half* __restrict__ Bw = G1 ? g_wup : g_wdn;

    const uint32_t sb = smem_u32(smem);

    // ---- cp.async: 2 A-chunks + 4 B-chunks per thread (16B each)
    const __half* a_src[2]; uint32_t a_dst[2];
    #pragma unroll
    for (int i = 0; i < 2; i++) {
        int idx = tid + i * 512;               // 0..1023
        int row = idx >> 3, ch = idx & 7;      // 128 rows x 8 chunks
        uint32_t sw = row * 128 + ((ch ^ (row & 7)) << 4);
        a_dst[i] = sw;
        a_src[i] = A + (size_t)(m0 + row) * KTOT + ch * 8;
    }
    const __half* b_src[4]; uint32_t b_dst[4];
    #pragma unroll
    for (int i = 0; i < 4; i++) {
        int idx = tid + i * 512;               // 0..2047
        int row = idx >> 3, ch = idx & 7;      // 256 rows x 8 chunks
        uint32_t sw = row * 128 + ((ch ^ (row & 7)) << 4);
        b_dst[i] = A_BYTES + sw;
        size_t grow;
        if (G1) {
            int h = blockIdx.y * 128 + (row >> 1);
            grow = (size_t)e * (2 * H_FF) + ((row & 1) ? (size_t)(H_FF + h) : (size_t)h);
        } else {
            grow = (size_t)e * D_IN + (size_t)(blockIdx.y * 256 + row);
        }
        b_src[i] = Bw + grow * KTOT + ch * 8;
    }

    auto load_stage = [&](int s, int kc) {
        uint32_t base = sb + s * STAGE_BYTES;
        int koff = kc * BK;
        #pragma unroll
        for (int i = 0; i < 2; i++) cp_async16(base + a_dst[i], a_src[i] + koff);
        #pragma unroll
        for (int i = 0; i < 4; i++) cp_async16(base + b_dst[i], b_src[i] + koff);
    };

    // ---- ldmatrix per-lane address pieces
    const int lrx = lid & 7;
    uint32_t a_rowoff[4], b_rowoff[2];
    #pragma unroll
    for (int mb = 0; mb < 4; mb++)
        a_rowoff[mb] = (uint32_t)(wm * 64 + mb * 16 + (lid & 15)) * 128;
    #pragma unroll
    for (int nb2 = 0; nb2 < 2; nb2++)
        b_rowoff[nb2] = A_BYTES + (uint32_t)(wn * 32 + nb2 * 16 + ((lid >> 4) << 3) + (lid & 7)) * 128;
    const int ahi = lid >> 4;            // A chunk hi bit
    const int bhi = (lid >> 3) & 1;      // B chunk hi bit

    float c[4][4][4];
    #pragma unroll
    for (int mb = 0; mb < 4; mb++)
        #pragma unroll
        for (int nb = 0; nb < 4; nb++)
            #pragma unroll
            for (int j = 0; j < 4; j++) c[mb][nb][j] = 0.f;

    auto compute_ktile = [&](int s) {
        const uint32_t stg = sb + s * STAGE_BYTES;
        #pragma unroll
        for (int ks = 0; ks < 4; ks++) {
            uint32_t a[4][4], b[2][4];
            #pragma unroll
            for (int mb = 0; mb < 4; mb++)
                ldsm4(a[mb], stg + a_rowoff[mb] + (uint32_t)(((ks * 2 + ahi) ^ lrx) << 4));
            #pragma unroll
            for (int nb2 = 0; nb2 < 2; nb2++)
                ldsm4(b[nb2], stg + b_rowoff[nb2] + (uint32_t)(((ks * 2 + bhi) ^ lrx) << 4));
            #pragma unroll
            for (int mb = 0; mb < 4; mb++) {
                #pragma unroll
                for (int nb = 0; nb < 4; nb++)
                    mma16816(c[mb][nb], a[mb], b[nb >> 1][(nb & 1) * 2], b[nb >> 1][(nb & 1) * 2 + 1]);
            }
        }
    };

    // ---- prologue: 2 stages in flight
    load_stage(0, 0); cp_commit();
    load_stage(1, 1); cp_commit();

    // ---- pairwise mainloop: one barrier per 2 k-tiles
    for (int kt = 0; kt < KITERS; kt += 2) {
        cp_wait0();
        __syncthreads();
        if (kt + 2 < KITERS) { load_stage((kt + 2) & 3, kt + 2); cp_commit(); }
        if (kt + 3 < KITERS) { load_stage((kt + 3) & 3, kt + 3); cp_commit(); }
        compute_ktile(kt & 3);
        compute_ktile((kt + 1) & 3);
    }
    __syncthreads();   // protect smem reuse by epilogue staging

    // ---- epilogue
    if (G1) {
        // SwiGLU -> stage fp16 to smem [128 rows][128 halfs, stride 136] -> coalesced copy out
        __half* acts = (__half*)smem;
        const int n0h = blockIdx.y * 128;
        #pragma unroll
        for (int mb = 0; mb < 4; mb++) {
            #pragma unroll
            for (int nb = 0; nb < 4; nb++) {
                int hl = wn * 16 + nb * 4 + (lid & 3);
                int r0 = wm * 64 + mb * 16 + (lid >> 2);
                float g0 = c[mb][nb][0], u0 = c[mb][nb][1];
                float g1 = c[mb][nb][2], u1 = c[mb][nb][3];
                float v0 = u0 * g0 / (1.f + __expf(-g0));
                float v1 = u1 * g1 / (1.f + __expf(-g1));
                acts[r0 * 136 + hl]       = __float2half_rn(v0);
                acts[(r0 + 8) * 136 + hl] = __float2half_rn(v1);
            }
        }
        __syncthreads();
        for (int idx = tid; idx < 128 * 16; idx += GEMM_THREADS) {
            int row = idx >> 4, q = idx & 15;
            if (m0 + row < m1) {
                uint4 v = *(const uint4*)((const char*)smem + row * 272 + q * 16);
                *(uint4*)(g_act + (size_t)(m0 + row) * H_FF + n0h + q * 8) = v;
            }
        }
    } else {
        const int n0 = blockIdx.y * 256;
        #pragma unroll
        for (int mb = 0; mb < 4; mb++) {
            int r0 = m0 + wm * 64 + mb * 16 + (lid >> 2);
            int r1 = r0 + 8;
            bool v0 = r0 < m1, v1 = r1 < m1;
            int tk0 = 0, tk1 = 0; float w0 = 0.f, w1 = 0.f;
            if (v0) { tk0 = g_rtok[r0]; w0 = g_rw[r0]; }
            if (v1) { tk1 = g_rtok[r1]; w1 = g_rw[r1]; }
            float* p0 = out + (size_t)tk0 * D_IN;
            float* p1 = out + (size_t)tk1 * D_IN;
            #pragma unroll
            for (int nb = 0; nb < 4; nb++) {
                int col = n0 + wn * 32 + nb * 8 + (lid & 3) * 2;
                if (v0) redg_v2(p0 + col, w0 * c[mb][nb][0], w0 * c[mb][nb][1]);
                if (v1) redg_v2(p1 + col, w1 * c[mb][nb][2], w1 * c[mb][nb][3]);
            }
        }
    }
}

// ---------------- launch ----------------
extern "C" void kernel_launch(void* const* d_in, const int* in_sizes, int n_in,
                              void* d_out, int out_size) {
    const float* x   = (const float*)d_in[0];   // [8192, 2048]
    const float* tw  = (const float*)d_in[1];   // [8192, 2]
    const float* wup = (const float*)d_in[2];   // [8, 11264, 2048]
    const float* wdn = (const float*)d_in[3];   // [8, 2048, 5632]
    const int*   ids = (const int*)d_in[4];     // [8192, 2]
    float* out = (float*)d_out;                 // [8192, 2048]

    cudaFuncSetAttribute(k_gemm<true>,  cudaFuncAttributeMaxDynamicSharedMemorySize, SMEM_TOTAL);
    cudaFuncSetAttribute(k_gemm<false>, cudaFuncAttributeMaxDynamicSharedMemorySize, SMEM_TOTAL);

    k_hist<<<1, 1024>>>(ids);                                              // #1
    k_prep<<<PAIRS + CONVUP_BLOCKS + ZERO_BLOCKS, 256>>>(x, tw, ids, wup, out); // #2
    k_gemm<true ><<<dim3(MAX_TILES, G1_YTILES + 1), GEMM_THREADS, SMEM_TOTAL>>>(nullptr, wdn); // #3
    k_gemm<false><<<dim3(MAX_TILES, D_IN / 256), GEMM_THREADS, SMEM_TOTAL>>>(out, nullptr);    // #4 (profiled)
}